// round 16
// baseline (speedup 1.0000x reference)
#include <cuda_runtime.h>
#include <limits.h>

// Problem constants (fixed by setup_inputs)
#define N_PERK 16384
#define NQK    4096      // B * M_PER
#define CINF   16
#define NS0    16
#define NS1    32
#define NT0    65536     // NQK * NS0
#define NT1    131072    // NQK * NS1

// channel offsets into the 144-wide BN stat arrays
#define OFF_S0L1 0
#define OFF_S0L2 16
#define OFF_S1L1 48
#define OFF_S1L2 80

#define GRIDR  10
#define NCELLS 1000
#define CAP1   768
#define CAP0   192
#define NBG    128       // gridbuild blocks (co-resident: <=148 SMs)
#define NB_MLP 296       // mlp blocks: 2/SM x 148 enforced by __launch_bounds__(256,2)

// ---------------- scratch (device globals; no allocation allowed) ----------
struct Scratch {
    int      cellcnt[2016];
    int      cellofs[2016];
    double   sum[144];
    double   sqs[144];
    unsigned wc1, wc2;     // work-steal counters (zeroed each run)
};
__device__ Scratch d_scr;
__device__ unsigned d_bar[4];          // monotonic barrier counters (never reset)
__device__ int    d_cellstart[2048];
__device__ float4 d_pts4 [2 * N_PERK]; // original order: (x,y,z,|p|^2)
__device__ float4 d_cpts4[2 * N_PERK]; // cell-sorted:    (x,y,z,idx_bits)
__device__ float  d_g0 [19 * NT0];
__device__ float  d_g1 [19 * NT1];
__device__ float  d_xa0[16 * NT0];
__device__ float  d_xa1[32 * NT1];
__device__ float  d_mx [NQK * 96];
__device__ float  d_mn [NQK * 96];

// ---------------- graph-replay-safe software grid barrier ------------------
__device__ __forceinline__ void gridbar(int i, unsigned nb)
{
    __syncthreads();
    if (threadIdx.x == 0) {
        __threadfence();
        unsigned t = atomicAdd(&d_bar[i], 1u);
        unsigned target = (t / nb + 1u) * nb;
        while (*(volatile unsigned*)&d_bar[i] < target)
            __nanosleep(32);
        __threadfence();
    }
    __syncthreads();
}

// ---------------- kernel 0: zero scratch + pack/count + scan/scatter -------
__global__ void __launch_bounds__(256) gridbuild_kernel(
    const float* __restrict__ xyz)
{
    __shared__ int sstart[2048];
    __shared__ int warpsum[8], warpbase[8];

    int t   = threadIdx.x;
    int gi  = blockIdx.x * 256 + t;        // 0..32767
    int lane = t & 31, w = t >> 5;

    {   // phase A: zero scratch (includes work-steal counters)
        const int n_ints = (int)(sizeof(Scratch) / sizeof(int));
        if (gi < n_ints) ((int*)&d_scr)[gi] = 0;
    }
    gridbar(0, NBG);

    // phase B: pack + count
    float4 myp;
    int mycell;
    {
        float x = xyz[gi*3+0], y = xyz[gi*3+1], z = xyz[gi*3+2];
        myp = make_float4(x, y, z, fmaf(z, z, fmaf(y, y, x*x)));
        d_pts4[gi] = myp;
        int cx = min(GRIDR-1, max(0, (int)(x * 10.f)));
        int cy = min(GRIDR-1, max(0, (int)(y * 10.f)));
        int cz = min(GRIDR-1, max(0, (int)(z * 10.f)));
        mycell = (gi >> 14) * NCELLS + (cz * GRIDR + cy) * GRIDR + cx;
        atomicAdd(&d_scr.cellcnt[mycell], 1);
    }
    gridbar(1, NBG);

    // phase C: per-block redundant smem scan + scatter
    int v[8];
    int loc = 0;
    int base = t * 8;
    #pragma unroll
    for (int j = 0; j < 8; j++) {
        int k = base + j;
        int c = (k < 2 * NCELLS) ? d_scr.cellcnt[k] : 0;
        v[j] = loc;
        loc += c;
    }
    int inc = loc;
    #pragma unroll
    for (int d = 1; d < 32; d <<= 1) {
        int x = __shfl_up_sync(0xffffffffu, inc, d);
        if (lane >= d) inc += x;
    }
    if (lane == 31) warpsum[w] = inc;
    __syncthreads();
    if (t == 0) {
        int s = 0;
        #pragma unroll
        for (int i = 0; i < 8; i++) { warpbase[i] = s; s += warpsum[i]; }
    }
    __syncthreads();
    int tbase = warpbase[w] + (inc - loc);
    #pragma unroll
    for (int j = 0; j < 8; j++)
        sstart[base + j] = tbase + v[j];
    __syncthreads();

    if (blockIdx.x == 0)
        for (int k = t; k <= 2 * NCELLS; k += 256)
            d_cellstart[k] = (k < 2048) ? sstart[k] : 0;

    {
        int pos = sstart[mycell] + atomicAdd(&d_scr.cellofs[mycell], 1);
        d_cpts4[pos] = make_float4(myp.x, myp.y, myp.z,
                                   __int_as_float(gi & (N_PERK - 1)));
    }
}

// ---------------- select k smallest values from cand[cnt] ------------------
__device__ __forceinline__ int select_k(const int* __restrict__ cand, int cnt,
                                        const int* __restrict__ bc,
                                        int* __restrict__ sel2,
                                        int* __restrict__ fin,
                                        int k, int lane, unsigned low, int shift)
{
    if (cnt <= k) {
        for (int i = lane; i < cnt; i += 32) fin[i] = cand[i];
        return cnt;
    }
    int p = bc[lane];
    #pragma unroll
    for (int d = 1; d < 32; d <<= 1) {
        int t = __shfl_up_sync(0xffffffffu, p, d);
        if (lane >= d) p += t;
    }
    unsigned mk = __ballot_sync(0xffffffffu, p >= k);
    int bstar = __ffs(mk) - 1;
    int base  = (bstar > 0) ? __shfl_sync(0xffffffffu, p, bstar - 1) : 0;
    int need  = k - base;
    int B0 = bstar << shift, B1 = (bstar + 1) << shift;

    int n_auto = 0, n_mid = 0;
    for (int i0 = 0; i0 < cnt; i0 += 32) {
        int i = i0 + lane;
        int v = (i < cnt) ? cand[i] : INT_MAX;
        bool a = (v < B0);
        bool m = (v >= B0) && (v < B1);
        unsigned ma = __ballot_sync(0xffffffffu, a);
        unsigned mm = __ballot_sync(0xffffffffu, m);
        if (a) fin[n_auto + __popc(ma & low)] = v;
        else if (m) {
            int pos = n_mid + __popc(mm & low);
            if (pos < 64) sel2[pos] = v;
        }
        n_auto += __popc(ma);
        n_mid  += __popc(mm);
    }
    if (n_mid > 64) n_mid = 64;
    __syncwarp();

    int last = -1;
    for (int j = 0; j < need; j++) {
        int v = INT_MAX;
        for (int i = lane; i < n_mid; i += 32) {
            int x = sel2[i];
            if (x > last && x < v) v = x;
        }
        #pragma unroll
        for (int d = 16; d; d >>= 1)
            v = min(v, __shfl_xor_sync(0xffffffffu, v, d));
        fin[base + j] = v;
        last = v;
    }
    return k;
}

// ---------------- kernel 1: block-per-query dual-scale ball query ----------
// Hot loop maintains ONLY the r=0.2 candidate list; r=0.1 membership is a
// flag in bit 0 ((idx<<1)|ok0). Warp 1 filters the flagged subset post-scan.
__global__ void __launch_bounds__(128) bq_block_kernel(
    const float* __restrict__ nxyz, const float* __restrict__ feat)
{
    __shared__ int cand1[CAP1], cand0[CAP0];
    __shared__ int bc1[32], bc0[32];
    __shared__ int sel2a[64], sel2b[64];
    __shared__ int fin1[NS1], fin0[NS0];
    __shared__ int scnt1, slmin1, slmin0, m1n_s, m0n_s;

    int tid  = threadIdx.x;
    int wid  = tid >> 5;
    int lane = tid & 31;
    unsigned low = (1u << lane) - 1u;

    int q = blockIdx.x;
    int b = q >> 11;
    int nbase = b << 14;

    if (tid < 32) { bc1[tid] = 0; bc0[tid] = 0; }
    if (tid == 0) { scnt1 = 0; slmin1 = INT_MAX; slmin0 = INT_MAX; }
    __syncthreads();

    float qx = nxyz[q*3+0], qy = nxyz[q*3+1], qz = nxyz[q*3+2];
    float q2 = fmaf(qz, qz, fmaf(qy, qy, qx*qx));

    int cy = min(GRIDR-1, max(0, (int)(qy * 10.f)));
    int cz = min(GRIDR-1, max(0, (int)(qz * 10.f)));
    int zlo = max(0, cz-2), zhi = min(GRIDR-1, cz+2);
    int ylo = max(0, cy-2), yhi = min(GRIDR-1, cy+2);
    int nz = zhi - zlo + 1, ny = yhi - ylo + 1;

    const float RP2 = 0.04f + 1e-4f;
    int lmin1 = INT_MAX;

    for (int ri = wid; ri < nz * ny; ri += 4) {
        int zz = zlo + ri / ny;
        int yy = ylo + ri % ny;
        float dz = fmaxf(0.f, fmaxf(zz * 0.1f - qz, qz - (zz+1) * 0.1f));
        float dy = fmaxf(0.f, fmaxf(yy * 0.1f - qy, qy - (yy+1) * 0.1f));
        float r2 = fmaf(dy, dy, dz * dz);
        if (r2 >= RP2) continue;
        float dxm = sqrtf(RP2 - r2);
        int xlo = max(0, (int)floorf((qx - dxm) * 10.f));
        int xhi = min(GRIDR-1, (int)floorf((qx + dxm) * 10.f));
        if (xlo > xhi) continue;
        int row = b * NCELLS + (zz * GRIDR + yy) * GRIDR;
        int s = d_cellstart[row + xlo];
        int e = d_cellstart[row + xhi + 1];
        for (int i0 = s; i0 < e; i0 += 64) {
            int ia = i0 + lane;
            int ib = ia + 32;
            bool oka1 = false, okb1 = false;
            int va = 0, vb = 0;
            if (ia < e) {
                float4 p = d_cpts4[ia];
                int idx = __float_as_int(p.w);
                float p2 = fmaf(p.z, p.z, fmaf(p.y, p.y, p.x*p.x));
                float dt = fmaf(qz, p.z, fmaf(qy, p.y, qx*p.x));
                float d2 = fmaf(-2.f, dt, q2 + p2);
                oka1 = d2 < 0.04f;
                va = (idx << 1) | (d2 < 0.01f ? 1 : 0);
            }
            if (ib < e) {
                float4 p = d_cpts4[ib];
                int idx = __float_as_int(p.w);
                float p2 = fmaf(p.z, p.z, fmaf(p.y, p.y, p.x*p.x));
                float dt = fmaf(qz, p.z, fmaf(qy, p.y, qx*p.x));
                float d2 = fmaf(-2.f, dt, q2 + p2);
                okb1 = d2 < 0.04f;
                vb = (idx << 1) | (d2 < 0.01f ? 1 : 0);
            }
            unsigned m1a = __ballot_sync(0xffffffffu, oka1);
            unsigned m1b = __ballot_sync(0xffffffffu, okb1);
            int c1a = __popc(m1a), tot1 = c1a + __popc(m1b);
            if (tot1) {
                int bpos = 0;
                if (lane == 0) bpos = atomicAdd(&scnt1, tot1);
                bpos = __shfl_sync(0xffffffffu, bpos, 0);
                if (oka1) {
                    lmin1 = min(lmin1, va);
                    int pos = bpos + __popc(m1a & low);
                    if (pos < CAP1) { cand1[pos] = va; atomicAdd(&bc1[va >> 10], 1); }
                }
                if (okb1) {
                    lmin1 = min(lmin1, vb);
                    int pos = bpos + c1a + __popc(m1b & low);
                    if (pos < CAP1) { cand1[pos] = vb; atomicAdd(&bc1[vb >> 10], 1); }
                }
            }
        }
    }
    #pragma unroll
    for (int d = 16; d; d >>= 1)
        lmin1 = min(lmin1, __shfl_xor_sync(0xffffffffu, lmin1, d));
    if (lane == 0) atomicMin(&slmin1, lmin1);
    __syncthreads();

    if (wid == 0) {
        int n = select_k(cand1, min(scnt1, CAP1), bc1, sel2a, fin1, NS1,
                         lane, low, 10);
        if (lane == 0) m1n_s = n;
    } else if (wid == 1) {
        // filter flagged (r<0.1) entries out of cand1 into cand0
        int cnt1c = min(scnt1, CAP1);
        int n0 = 0, lm0 = INT_MAX;
        for (int i0 = 0; i0 < cnt1c; i0 += 32) {
            int i = i0 + lane;
            int v = (i < cnt1c) ? cand1[i] : 0;
            bool f = (i < cnt1c) && (v & 1);
            unsigned mf = __ballot_sync(0xffffffffu, f);
            if (f) {
                lm0 = min(lm0, v);
                int pos = n0 + __popc(mf & low);
                if (pos < CAP0) { cand0[pos] = v; atomicAdd(&bc0[v >> 10], 1); }
            }
            n0 += __popc(mf);
        }
        #pragma unroll
        for (int d = 16; d; d >>= 1)
            lm0 = min(lm0, __shfl_xor_sync(0xffffffffu, lm0, d));
        if (lane == 0) slmin0 = lm0;
        __syncwarp();
        int n = select_k(cand0, min(n0, CAP0), bc0, sel2b, fin0, NS0,
                         lane, low, 10);
        if (lane == 0) m0n_s = n;
    }
    __syncthreads();

    if (wid == 0) {   // scale-1 grouping
        int m1n = m1n_s;
        int sidx = q * NS1 + lane;
        float g[19];
        if (m1n == 0) {
            #pragma unroll
            for (int c = 0; c < 19; c++) g[c] = 0.f;
        } else {
            int id = ((lane < m1n) ? fin1[lane] : slmin1) >> 1;
            float4 p = d_pts4[nbase + id];
            g[0] = p.x - qx; g[1] = p.y - qy; g[2] = p.z - qz;
            const float4* f = (const float4*)(feat + (size_t)(nbase + id) * CINF);
            float4 f0 = f[0], f1 = f[1], f2 = f[2], f3 = f[3];
            g[3]=f0.x; g[4]=f0.y; g[5]=f0.z; g[6]=f0.w;
            g[7]=f1.x; g[8]=f1.y; g[9]=f1.z; g[10]=f1.w;
            g[11]=f2.x; g[12]=f2.y; g[13]=f2.z; g[14]=f2.w;
            g[15]=f3.x; g[16]=f3.y; g[17]=f3.z; g[18]=f3.w;
        }
        #pragma unroll
        for (int c = 0; c < 19; c++) d_g1[c * NT1 + sidx] = g[c];
    } else if (wid == 1 && lane < NS0) {   // scale-0 grouping
        int m0n = m0n_s;
        int sidx = q * NS0 + lane;
        float g[19];
        if (m0n == 0) {
            #pragma unroll
            for (int c = 0; c < 19; c++) g[c] = 0.f;
        } else {
            int id = ((lane < m0n) ? fin0[lane] : slmin0) >> 1;
            float4 p = d_pts4[nbase + id];
            g[0] = p.x - qx; g[1] = p.y - qy; g[2] = p.z - qz;
            const float4* f = (const float4*)(feat + (size_t)(nbase + id) * CINF);
            float4 f0 = f[0], f1 = f[1], f2 = f[2], f3 = f[3];
            g[3]=f0.x; g[4]=f0.y; g[5]=f0.z; g[6]=f0.w;
            g[7]=f1.x; g[8]=f1.y; g[9]=f1.z; g[10]=f1.w;
            g[11]=f2.x; g[12]=f2.y; g[13]=f2.z; g[14]=f2.w;
            g[15]=f3.x; g[16]=f3.y; g[17]=f3.z; g[18]=f3.w;
        }
        #pragma unroll
        for (int c = 0; c < 19; c++) d_g0[c * NT0 + sidx] = g[c];
    }
}

// ---------------- layer-1 GEMV body (SPT=2, writes xa + stats) -------------
template<int CIN, int CINP, int COUT>
__device__ __forceinline__ void gemv1_body(
    int bid, const float* __restrict__ in, int ntot,
    const float* __restrict__ W, float* __restrict__ out, int off,
    float* __restrict__ sW, float* __restrict__ shm, float* __restrict__ shq)
{
    for (int i = threadIdx.x; i < COUT * CINP; i += 256) {
        int o = i / CINP, c = i % CINP;
        sW[i] = (c < CIN) ? W[o * CIN + c] : 0.f;
    }
    for (int i = threadIdx.x; i < COUT; i += 256) { shm[i] = 0.f; shq[i] = 0.f; }
    __syncthreads();

    int s    = (bid * 256 + threadIdx.x) * 2;
    int lane = threadIdx.x & 31;

    float2 x[CINP];
    #pragma unroll
    for (int c = 0; c < CINP; c++)
        x[c] = (c < CIN) ? *(const float2*)&in[(size_t)c * ntot + s]
                         : make_float2(0.f, 0.f);

    const float4* sW4 = (const float4*)sW;
    #pragma unroll
    for (int o = 0; o < COUT; o++) {
        float ax = 0.f, ay = 0.f;
        #pragma unroll
        for (int c4 = 0; c4 < CINP / 4; c4++) {
            float4 wv = sW4[o * (CINP / 4) + c4];
            ax = fmaf(x[c4*4+0].x, wv.x, ax); ay = fmaf(x[c4*4+0].y, wv.x, ay);
            ax = fmaf(x[c4*4+1].x, wv.y, ax); ay = fmaf(x[c4*4+1].y, wv.y, ay);
            ax = fmaf(x[c4*4+2].x, wv.z, ax); ay = fmaf(x[c4*4+2].y, wv.z, ay);
            ax = fmaf(x[c4*4+3].x, wv.w, ax); ay = fmaf(x[c4*4+3].y, wv.w, ay);
        }
        *(float2*)&out[(size_t)o * ntot + s] = make_float2(ax, ay);
        float sm = ax + ay;
        float sq = fmaf(ax, ax, ay * ay);
        #pragma unroll
        for (int d = 16; d; d >>= 1) {
            sm += __shfl_down_sync(0xffffffffu, sm, d);
            sq += __shfl_down_sync(0xffffffffu, sq, d);
        }
        if (lane == 0) { atomicAdd(&shm[o], sm); atomicAdd(&shq[o], sq); }
    }
    __syncthreads();
    if (threadIdx.x < COUT) {
        atomicAdd(&d_scr.sum[off + threadIdx.x], (double)shm[threadIdx.x]);
        atomicAdd(&d_scr.sqs[off + threadIdx.x], (double)shq[threadIdx.x]);
    }
    __syncthreads();
}

// ---------------- layer-2 body: BN/ReLU in + GEMV + stats + extremals ------
template<int CIN, int COUT, int NS, int COLOFF>
__device__ __forceinline__ void gemv2_body(
    int bid, const float* __restrict__ in, int ntot,
    const float* __restrict__ W,
    const float* __restrict__ gamma_, const float* __restrict__ beta_,
    float pN, int poff, int off,
    float* __restrict__ sW, float* __restrict__ sS, float* __restrict__ sB,
    float* __restrict__ shm, float* __restrict__ shq)
{
    for (int i = threadIdx.x; i < COUT * CIN; i += 256)
        sW[i] = W[i];
    for (int i = threadIdx.x; i < COUT; i += 256) { shm[i] = 0.f; shq[i] = 0.f; }
    for (int i = threadIdx.x; i < CIN; i += 256) {
        double inv  = 1.0 / (double)pN;
        double mean = d_scr.sum[poff + i] * inv;
        double var  = d_scr.sqs[poff + i] * inv - mean * mean;
        double sc   = (double)gamma_[i] * rsqrt(var + 1e-5);
        sS[i] = (float)sc;
        sB[i] = (float)((double)beta_[i] - mean * sc);
    }
    __syncthreads();

    int s    = (bid * 256 + threadIdx.x) * 2;
    int lane = threadIdx.x & 31;
    int q    = s / NS;

    float2 x[CIN];
    #pragma unroll
    for (int c = 0; c < CIN; c++) {
        float2 v = *(const float2*)&in[(size_t)c * ntot + s];
        v.x = fmaxf(fmaf(v.x, sS[c], sB[c]), 0.f);
        v.y = fmaxf(fmaf(v.y, sS[c], sB[c]), 0.f);
        x[c] = v;
    }

    const float4* sW4 = (const float4*)sW;
    #pragma unroll
    for (int o = 0; o < COUT; o++) {
        float ax = 0.f, ay = 0.f;
        #pragma unroll
        for (int c4 = 0; c4 < CIN / 4; c4++) {
            float4 wv = sW4[o * (CIN / 4) + c4];
            ax = fmaf(x[c4*4+0].x, wv.x, ax); ay = fmaf(x[c4*4+0].y, wv.x, ay);
            ax = fmaf(x[c4*4+1].x, wv.y, ax); ay = fmaf(x[c4*4+1].y, wv.y, ay);
            ax = fmaf(x[c4*4+2].x, wv.z, ax); ay = fmaf(x[c4*4+2].y, wv.z, ay);
            ax = fmaf(x[c4*4+3].x, wv.w, ax); ay = fmaf(x[c4*4+3].y, wv.w, ay);
        }
        float sm = ax + ay;
        float sq = fmaf(ax, ax, ay * ay);
        #pragma unroll
        for (int d = 16; d; d >>= 1) {
            sm += __shfl_down_sync(0xffffffffu, sm, d);
            sq += __shfl_down_sync(0xffffffffu, sq, d);
        }
        if (lane == 0) { atomicAdd(&shm[o], sm); atomicAdd(&shq[o], sq); }

        float mx = fmaxf(ax, ay), mn = fminf(ax, ay);
        #pragma unroll
        for (int d = 1; d < NS / 2; d <<= 1) {
            mx = fmaxf(mx, __shfl_xor_sync(0xffffffffu, mx, d));
            mn = fminf(mn, __shfl_xor_sync(0xffffffffu, mn, d));
        }
        if ((lane & (NS / 2 - 1)) == 0) {
            d_mx[q * 96 + COLOFF + o] = mx;
            d_mn[q * 96 + COLOFF + o] = mn;
        }
    }
    __syncthreads();
    if (threadIdx.x < COUT) {
        atomicAdd(&d_scr.sum[off + threadIdx.x], (double)shm[threadIdx.x]);
        atomicAdd(&d_scr.sqs[off + threadIdx.x], (double)shq[threadIdx.x]);
    }
    __syncthreads();
}

// ---------------- kernel 2: persistent MLP (work-stealing, fused finalize) -
__global__ void __launch_bounds__(256, 2) mlp_kernel(
    const float* __restrict__ w10, const float* __restrict__ w00,
    const float* __restrict__ w11, const float* __restrict__ g10,
    const float* __restrict__ b10,
    const float* __restrict__ w01, const float* __restrict__ g00,
    const float* __restrict__ b00,
    const float* __restrict__ g11, const float* __restrict__ b11,
    const float* __restrict__ g01, const float* __restrict__ b01,
    const float* __restrict__ nxyz, int out_off, float* __restrict__ out)
{
    __shared__ __align__(16) float sW[64 * 32];
    __shared__ float sS[32], sB[32], shm[64], shq[64];
    __shared__ float ps[96], pb[96];
    __shared__ int sc;

    // ---- layer 1: work-stealing over 384 chunks ----
    for (;;) {
        if (threadIdx.x == 0) sc = (int)atomicAdd(&d_scr.wc1, 1u);
        __syncthreads();
        int c = sc;
        if (c >= 384) break;
        if (c < 256)
            gemv1_body<19, 20, 32>(c, d_g1, NT1, w10, d_xa1, OFF_S1L1,
                                   sW, shm, shq);
        else
            gemv1_body<19, 20, 16>(c - 256, d_g0, NT0, w00, d_xa0, OFF_S0L1,
                                   sW, shm, shq);
    }
    gridbar(2, NB_MLP);

    // ---- layer 2: work-stealing over 384 chunks ----
    for (;;) {
        if (threadIdx.x == 0) sc = (int)atomicAdd(&d_scr.wc2, 1u);
        __syncthreads();
        int c = sc;
        if (c >= 384) break;
        if (c < 256)
            gemv2_body<32, 64, NS1, 32>(c, d_xa1, NT1, w11, g10, b10,
                                        (float)NT1, OFF_S1L1, OFF_S1L2,
                                        sW, sS, sB, shm, shq);
        else
            gemv2_body<16, 32, NS0, 0>(c - 256, d_xa0, NT0, w01, g00, b00,
                                       (float)NT0, OFF_S0L1, OFF_S0L2,
                                       sW, sS, sB, shm, shq);
    }
    gridbar(3, NB_MLP);

    // ---- every block computes the 96 layer-2 BN params (cheap) ----
    if (threadIdx.x < 96) {
        int t = threadIdx.x;
        int off; float pN, gam, bet;
        if (t < 32) { off = OFF_S0L2 + t; pN = (float)NT0; gam = g01[t]; bet = b01[t]; }
        else        { off = OFF_S1L2 + t - 32; pN = (float)NT1; gam = g11[t-32]; bet = b11[t-32]; }
        double inv  = 1.0 / (double)pN;
        double mean = d_scr.sum[off] * inv;
        double var  = d_scr.sqs[off] * inv - mean * mean;
        double scd  = (double)gam * rsqrt(var + 1e-5);
        // map scratch offset layout -> output column layout:
        // cols [0,32) = scale0 (t<32), cols [32,96) = scale1 (t>=32)
        ps[t] = (float)scd;
        pb[t] = (float)((double)bet - mean * scd);
    }
    __syncthreads();

    // ---- finalize: nxyz copy + BN+ReLU on extremals ----
    int total = out_off + NQK * 96;
    for (int idx = blockIdx.x * 256 + threadIdx.x; idx < total;
         idx += NB_MLP * 256) {
        if (idx < out_off) {
            out[idx] = nxyz[idx];
        } else {
            int k = idx - out_off;
            int col = k % 96;
            float scf = ps[col], bif = pb[col];
            float v = (scf >= 0.f) ? d_mx[k] : d_mn[k];
            out[idx] = fmaxf(fmaf(v, scf, bif), 0.f);
        }
    }
}

// ---------------- launch ----------------------------------------------------
extern "C" void kernel_launch(void* const* d_in, const int* in_sizes, int n_in,
                              void* d_out, int out_size)
{
    const float* xyz  = (const float*)d_in[0];
    const float* nxyz = (const float*)d_in[2];
    const float* feat = (const float*)d_in[4];
    const float* w00 = (const float*)d_in[5];
    const float* g00 = (const float*)d_in[6];
    const float* b00 = (const float*)d_in[7];
    const float* w01 = (const float*)d_in[8];
    const float* g01 = (const float*)d_in[9];
    const float* b01 = (const float*)d_in[10];
    const float* w10 = (const float*)d_in[11];
    const float* g10 = (const float*)d_in[12];
    const float* b10 = (const float*)d_in[13];
    const float* w11 = (const float*)d_in[14];
    const float* g11 = (const float*)d_in[15];
    const float* b11 = (const float*)d_in[16];
    float* out = (float*)d_out;

    int out_off = out_size - NQK * 96;
    if (out_off < 0) out_off = 0;

    gridbuild_kernel<<<NBG, 256>>>(xyz);                              // 1
    bq_block_kernel<<<NQK, 128>>>(nxyz, feat);                        // 2
    mlp_kernel<<<NB_MLP, 256>>>(w10, w00, w11, g10, b10,              // 3
                                w01, g00, b00, g11, b11, g01, b01,
                                nxyz, out_off, out);
}

// round 17
// speedup vs baseline: 1.0930x; 1.0930x over previous
#include <cuda_runtime.h>
#include <limits.h>

// Problem constants (fixed by setup_inputs)
#define N_PERK 16384
#define NQK    4096      // B * M_PER
#define CINF   16
#define NS0    16
#define NS1    32
#define NT0    65536     // NQK * NS0
#define NT1    131072    // NQK * NS1

// channel offsets into the 144-wide BN stat arrays
#define OFF_S0L1 0
#define OFF_S0L2 16
#define OFF_S1L1 48
#define OFF_S1L2 80

#define GRIDR  10
#define NCELLS 1000
#define CAP1   768
#define CAP0   192
#define NBG    128       // gridbuild blocks (co-resident: <=148 SMs)
#define NB_L2  384

// ---------------- scratch (device globals; loader-zeroed; every run
// restores zeros after last use, so no start-of-run memset is needed) -------
__device__ int      d_cellcnt[2016];
__device__ int      d_cellofs[2016];
__device__ double   d_sum[144];
__device__ double   d_sqs[144];
__device__ unsigned d_ctr2;
__device__ unsigned d_bar[2];          // monotonic barrier counters (never reset)
__device__ int    d_cellstart[2048];
__device__ float4 d_pts4 [2 * N_PERK]; // original order: (x,y,z,|p|^2)
__device__ float4 d_cpts4[2 * N_PERK]; // cell-sorted:    (x,y,z,idx_bits)
__device__ float  d_g0 [19 * NT0];
__device__ float  d_g1 [19 * NT1];
__device__ float  d_xa0[16 * NT0];
__device__ float  d_xa1[32 * NT1];
__device__ float  d_mx [NQK * 96];
__device__ float  d_mn [NQK * 96];
__device__ float  d_p2s[96], d_p2b[96];

// ---------------- graph-replay-safe software grid barrier ------------------
__device__ __forceinline__ void gridbar(int i, unsigned nb)
{
    __syncthreads();
    if (threadIdx.x == 0) {
        __threadfence();
        unsigned t = atomicAdd(&d_bar[i], 1u);
        unsigned target = (t / nb + 1u) * nb;
        while (*(volatile unsigned*)&d_bar[i] < target)
            __nanosleep(32);
        __threadfence();
    }
    __syncthreads();
}

// ---------------- kernel 0: pack/count + scan/scatter (one barrier) --------
// Relies on d_cellcnt/d_cellofs being zero on entry (loader-zeroed initially;
// re-zeroed by bq_block_kernel at the end of each run).
__global__ void __launch_bounds__(256) gridbuild_kernel(
    const float* __restrict__ xyz)
{
    __shared__ int sstart[2048];
    __shared__ int warpsum[8], warpbase[8];

    int t   = threadIdx.x;
    int gi  = blockIdx.x * 256 + t;        // 0..32767
    int lane = t & 31, w = t >> 5;

    // phase A: pack + count
    float4 myp;
    int mycell;
    {
        float x = xyz[gi*3+0], y = xyz[gi*3+1], z = xyz[gi*3+2];
        myp = make_float4(x, y, z, fmaf(z, z, fmaf(y, y, x*x)));
        d_pts4[gi] = myp;
        int cx = min(GRIDR-1, max(0, (int)(x * 10.f)));
        int cy = min(GRIDR-1, max(0, (int)(y * 10.f)));
        int cz = min(GRIDR-1, max(0, (int)(z * 10.f)));
        mycell = (gi >> 14) * NCELLS + (cz * GRIDR + cy) * GRIDR + cx;
        atomicAdd(&d_cellcnt[mycell], 1);
    }
    gridbar(0, NBG);

    // phase B: per-block redundant smem scan + scatter
    int v[8];
    int loc = 0;
    int base = t * 8;
    #pragma unroll
    for (int j = 0; j < 8; j++) {
        int k = base + j;
        int c = (k < 2 * NCELLS) ? d_cellcnt[k] : 0;
        v[j] = loc;
        loc += c;
    }
    int inc = loc;
    #pragma unroll
    for (int d = 1; d < 32; d <<= 1) {
        int x = __shfl_up_sync(0xffffffffu, inc, d);
        if (lane >= d) inc += x;
    }
    if (lane == 31) warpsum[w] = inc;
    __syncthreads();
    if (t == 0) {
        int s = 0;
        #pragma unroll
        for (int i = 0; i < 8; i++) { warpbase[i] = s; s += warpsum[i]; }
    }
    __syncthreads();
    int tbase = warpbase[w] + (inc - loc);
    #pragma unroll
    for (int j = 0; j < 8; j++)
        sstart[base + j] = tbase + v[j];
    __syncthreads();

    if (blockIdx.x == 0)
        for (int k = t; k <= 2 * NCELLS; k += 256)
            d_cellstart[k] = (k < 2048) ? sstart[k] : 0;

    {
        int pos = sstart[mycell] + atomicAdd(&d_cellofs[mycell], 1);
        d_cpts4[pos] = make_float4(myp.x, myp.y, myp.z,
                                   __int_as_float(gi & (N_PERK - 1)));
    }
}

// ---------------- select k smallest values from cand[cnt] ------------------
__device__ __forceinline__ int select_k(const int* __restrict__ cand, int cnt,
                                        const int* __restrict__ bc,
                                        int* __restrict__ sel2,
                                        int* __restrict__ fin,
                                        int k, int lane, unsigned low, int shift)
{
    if (cnt <= k) {
        for (int i = lane; i < cnt; i += 32) fin[i] = cand[i];
        return cnt;
    }
    int p = bc[lane];
    #pragma unroll
    for (int d = 1; d < 32; d <<= 1) {
        int t = __shfl_up_sync(0xffffffffu, p, d);
        if (lane >= d) p += t;
    }
    unsigned mk = __ballot_sync(0xffffffffu, p >= k);
    int bstar = __ffs(mk) - 1;
    int base  = (bstar > 0) ? __shfl_sync(0xffffffffu, p, bstar - 1) : 0;
    int need  = k - base;
    int B0 = bstar << shift, B1 = (bstar + 1) << shift;

    int n_auto = 0, n_mid = 0;
    for (int i0 = 0; i0 < cnt; i0 += 32) {
        int i = i0 + lane;
        int v = (i < cnt) ? cand[i] : INT_MAX;
        bool a = (v < B0);
        bool m = (v >= B0) && (v < B1);
        unsigned ma = __ballot_sync(0xffffffffu, a);
        unsigned mm = __ballot_sync(0xffffffffu, m);
        if (a) fin[n_auto + __popc(ma & low)] = v;
        else if (m) {
            int pos = n_mid + __popc(mm & low);
            if (pos < 64) sel2[pos] = v;
        }
        n_auto += __popc(ma);
        n_mid  += __popc(mm);
    }
    if (n_mid > 64) n_mid = 64;
    __syncwarp();

    int last = -1;
    for (int j = 0; j < need; j++) {
        int v = INT_MAX;
        for (int i = lane; i < n_mid; i += 32) {
            int x = sel2[i];
            if (x > last && x < v) v = x;
        }
        #pragma unroll
        for (int d = 16; d; d >>= 1)
            v = min(v, __shfl_xor_sync(0xffffffffu, v, d));
        fin[base + j] = v;
        last = v;
    }
    return k;
}

// ---------------- kernel 1: block-per-query dual-scale ball query ----------
// Hot loop maintains ONLY the r=0.2 candidate list; r=0.1 membership is a
// flag in bit 0 ((idx<<1)|ok0). Warp 1 filters the flagged subset post-scan.
// Blocks 0..31 additionally restore d_cellcnt/d_cellofs to zero for the next
// graph replay (gridbuild has completed by stream order).
__global__ void __launch_bounds__(128) bq_block_kernel(
    const float* __restrict__ nxyz, const float* __restrict__ feat)
{
    __shared__ int cand1[CAP1], cand0[CAP0];
    __shared__ int bc1[32], bc0[32];
    __shared__ int sel2a[64], sel2b[64];
    __shared__ int fin1[NS1], fin0[NS0];
    __shared__ int scnt1, slmin1, slmin0, m1n_s, m0n_s;

    int tid  = threadIdx.x;
    int wid  = tid >> 5;
    int lane = tid & 31;
    unsigned low = (1u << lane) - 1u;

    int q = blockIdx.x;
    int b = q >> 11;
    int nbase = b << 14;

    // zero-restore duty (63 ints per block over 64 blocks = 2*2016 ints)
    if (q < 64) {
        int base = q * 63;
        for (int i = tid; i < 63; i += 128) {
            int k = base + i;
            if (k < 2016) { d_cellcnt[k] = 0; d_cellofs[k] = 0; }
        }
    }

    if (tid < 32) { bc1[tid] = 0; bc0[tid] = 0; }
    if (tid == 0) { scnt1 = 0; slmin1 = INT_MAX; slmin0 = INT_MAX; }
    __syncthreads();

    float qx = nxyz[q*3+0], qy = nxyz[q*3+1], qz = nxyz[q*3+2];
    float q2 = fmaf(qz, qz, fmaf(qy, qy, qx*qx));

    int cy = min(GRIDR-1, max(0, (int)(qy * 10.f)));
    int cz = min(GRIDR-1, max(0, (int)(qz * 10.f)));
    int zlo = max(0, cz-2), zhi = min(GRIDR-1, cz+2);
    int ylo = max(0, cy-2), yhi = min(GRIDR-1, cy+2);
    int nz = zhi - zlo + 1, ny = yhi - ylo + 1;

    const float RP2 = 0.04f + 1e-4f;
    int lmin1 = INT_MAX;

    for (int ri = wid; ri < nz * ny; ri += 4) {
        int zz = zlo + ri / ny;
        int yy = ylo + ri % ny;
        float dz = fmaxf(0.f, fmaxf(zz * 0.1f - qz, qz - (zz+1) * 0.1f));
        float dy = fmaxf(0.f, fmaxf(yy * 0.1f - qy, qy - (yy+1) * 0.1f));
        float r2 = fmaf(dy, dy, dz * dz);
        if (r2 >= RP2) continue;
        float dxm = sqrtf(RP2 - r2);
        int xlo = max(0, (int)floorf((qx - dxm) * 10.f));
        int xhi = min(GRIDR-1, (int)floorf((qx + dxm) * 10.f));
        if (xlo > xhi) continue;
        int row = b * NCELLS + (zz * GRIDR + yy) * GRIDR;
        int s = d_cellstart[row + xlo];
        int e = d_cellstart[row + xhi + 1];
        for (int i0 = s; i0 < e; i0 += 64) {
            int ia = i0 + lane;
            int ib = ia + 32;
            bool oka1 = false, okb1 = false;
            int va = 0, vb = 0;
            if (ia < e) {
                float4 p = d_cpts4[ia];
                int idx = __float_as_int(p.w);
                float p2 = fmaf(p.z, p.z, fmaf(p.y, p.y, p.x*p.x));
                float dt = fmaf(qz, p.z, fmaf(qy, p.y, qx*p.x));
                float d2 = fmaf(-2.f, dt, q2 + p2);
                oka1 = d2 < 0.04f;
                va = (idx << 1) | (d2 < 0.01f ? 1 : 0);
            }
            if (ib < e) {
                float4 p = d_cpts4[ib];
                int idx = __float_as_int(p.w);
                float p2 = fmaf(p.z, p.z, fmaf(p.y, p.y, p.x*p.x));
                float dt = fmaf(qz, p.z, fmaf(qy, p.y, qx*p.x));
                float d2 = fmaf(-2.f, dt, q2 + p2);
                okb1 = d2 < 0.04f;
                vb = (idx << 1) | (d2 < 0.01f ? 1 : 0);
            }
            unsigned m1a = __ballot_sync(0xffffffffu, oka1);
            unsigned m1b = __ballot_sync(0xffffffffu, okb1);
            int c1a = __popc(m1a), tot1 = c1a + __popc(m1b);
            if (tot1) {
                int bpos = 0;
                if (lane == 0) bpos = atomicAdd(&scnt1, tot1);
                bpos = __shfl_sync(0xffffffffu, bpos, 0);
                if (oka1) {
                    lmin1 = min(lmin1, va);
                    int pos = bpos + __popc(m1a & low);
                    if (pos < CAP1) { cand1[pos] = va; atomicAdd(&bc1[va >> 10], 1); }
                }
                if (okb1) {
                    lmin1 = min(lmin1, vb);
                    int pos = bpos + c1a + __popc(m1b & low);
                    if (pos < CAP1) { cand1[pos] = vb; atomicAdd(&bc1[vb >> 10], 1); }
                }
            }
        }
    }
    #pragma unroll
    for (int d = 16; d; d >>= 1)
        lmin1 = min(lmin1, __shfl_xor_sync(0xffffffffu, lmin1, d));
    if (lane == 0) atomicMin(&slmin1, lmin1);
    __syncthreads();

    if (wid == 0) {
        int n = select_k(cand1, min(scnt1, CAP1), bc1, sel2a, fin1, NS1,
                         lane, low, 10);
        if (lane == 0) m1n_s = n;
    } else if (wid == 1) {
        // filter flagged (r<0.1) entries out of cand1 into cand0
        int cnt1c = min(scnt1, CAP1);
        int n0 = 0, lm0 = INT_MAX;
        for (int i0 = 0; i0 < cnt1c; i0 += 32) {
            int i = i0 + lane;
            int v = (i < cnt1c) ? cand1[i] : 0;
            bool f = (i < cnt1c) && (v & 1);
            unsigned mf = __ballot_sync(0xffffffffu, f);
            if (f) {
                lm0 = min(lm0, v);
                int pos = n0 + __popc(mf & low);
                if (pos < CAP0) { cand0[pos] = v; atomicAdd(&bc0[v >> 10], 1); }
            }
            n0 += __popc(mf);
        }
        #pragma unroll
        for (int d = 16; d; d >>= 1)
            lm0 = min(lm0, __shfl_xor_sync(0xffffffffu, lm0, d));
        if (lane == 0) slmin0 = lm0;
        __syncwarp();
        int n = select_k(cand0, min(n0, CAP0), bc0, sel2b, fin0, NS0,
                         lane, low, 10);
        if (lane == 0) m0n_s = n;
    }
    __syncthreads();

    if (wid == 0) {   // scale-1 grouping
        int m1n = m1n_s;
        int sidx = q * NS1 + lane;
        float g[19];
        if (m1n == 0) {
            #pragma unroll
            for (int c = 0; c < 19; c++) g[c] = 0.f;
        } else {
            int id = ((lane < m1n) ? fin1[lane] : slmin1) >> 1;
            float4 p = d_pts4[nbase + id];
            g[0] = p.x - qx; g[1] = p.y - qy; g[2] = p.z - qz;
            const float4* f = (const float4*)(feat + (size_t)(nbase + id) * CINF);
            float4 f0 = f[0], f1 = f[1], f2 = f[2], f3 = f[3];
            g[3]=f0.x; g[4]=f0.y; g[5]=f0.z; g[6]=f0.w;
            g[7]=f1.x; g[8]=f1.y; g[9]=f1.z; g[10]=f1.w;
            g[11]=f2.x; g[12]=f2.y; g[13]=f2.z; g[14]=f2.w;
            g[15]=f3.x; g[16]=f3.y; g[17]=f3.z; g[18]=f3.w;
        }
        #pragma unroll
        for (int c = 0; c < 19; c++) d_g1[c * NT1 + sidx] = g[c];
    } else if (wid == 1 && lane < NS0) {   // scale-0 grouping
        int m0n = m0n_s;
        int sidx = q * NS0 + lane;
        float g[19];
        if (m0n == 0) {
            #pragma unroll
            for (int c = 0; c < 19; c++) g[c] = 0.f;
        } else {
            int id = ((lane < m0n) ? fin0[lane] : slmin0) >> 1;
            float4 p = d_pts4[nbase + id];
            g[0] = p.x - qx; g[1] = p.y - qy; g[2] = p.z - qz;
            const float4* f = (const float4*)(feat + (size_t)(nbase + id) * CINF);
            float4 f0 = f[0], f1 = f[1], f2 = f[2], f3 = f[3];
            g[3]=f0.x; g[4]=f0.y; g[5]=f0.z; g[6]=f0.w;
            g[7]=f1.x; g[8]=f1.y; g[9]=f1.z; g[10]=f1.w;
            g[11]=f2.x; g[12]=f2.y; g[13]=f2.z; g[14]=f2.w;
            g[15]=f3.x; g[16]=f3.y; g[17]=f3.z; g[18]=f3.w;
        }
        #pragma unroll
        for (int c = 0; c < 19; c++) d_g0[c * NT0 + sidx] = g[c];
    }
}

// ---------------- layer-1 GEMV body (SPT=2, writes xa + stats) -------------
template<int CIN, int CINP, int COUT>
__device__ __forceinline__ void gemv1_body(
    int bid, const float* __restrict__ in, int ntot,
    const float* __restrict__ W, float* __restrict__ out, int off,
    float* __restrict__ sW, float* __restrict__ shm, float* __restrict__ shq)
{
    for (int i = threadIdx.x; i < COUT * CINP; i += 256) {
        int o = i / CINP, c = i % CINP;
        sW[i] = (c < CIN) ? W[o * CIN + c] : 0.f;
    }
    for (int i = threadIdx.x; i < COUT; i += 256) { shm[i] = 0.f; shq[i] = 0.f; }
    __syncthreads();

    int s    = (bid * 256 + threadIdx.x) * 2;
    int lane = threadIdx.x & 31;

    float2 x[CINP];
    #pragma unroll
    for (int c = 0; c < CINP; c++)
        x[c] = (c < CIN) ? *(const float2*)&in[(size_t)c * ntot + s]
                         : make_float2(0.f, 0.f);

    const float4* sW4 = (const float4*)sW;
    #pragma unroll
    for (int o = 0; o < COUT; o++) {
        float ax = 0.f, ay = 0.f;
        #pragma unroll
        for (int c4 = 0; c4 < CINP / 4; c4++) {
            float4 wv = sW4[o * (CINP / 4) + c4];
            ax = fmaf(x[c4*4+0].x, wv.x, ax); ay = fmaf(x[c4*4+0].y, wv.x, ay);
            ax = fmaf(x[c4*4+1].x, wv.y, ax); ay = fmaf(x[c4*4+1].y, wv.y, ay);
            ax = fmaf(x[c4*4+2].x, wv.z, ax); ay = fmaf(x[c4*4+2].y, wv.z, ay);
            ax = fmaf(x[c4*4+3].x, wv.w, ax); ay = fmaf(x[c4*4+3].y, wv.w, ay);
        }
        *(float2*)&out[(size_t)o * ntot + s] = make_float2(ax, ay);
        float sm = ax + ay;
        float sq = fmaf(ax, ax, ay * ay);
        #pragma unroll
        for (int d = 16; d; d >>= 1) {
            sm += __shfl_down_sync(0xffffffffu, sm, d);
            sq += __shfl_down_sync(0xffffffffu, sq, d);
        }
        if (lane == 0) { atomicAdd(&shm[o], sm); atomicAdd(&shq[o], sq); }
    }
    __syncthreads();
    if (threadIdx.x < COUT) {
        atomicAdd(&d_sum[off + threadIdx.x], (double)shm[threadIdx.x]);
        atomicAdd(&d_sqs[off + threadIdx.x], (double)shq[threadIdx.x]);
    }
}

// ---------------- kernel 2: fused layer-1 GEMVs (SPT=2, 384 blocks) --------
__global__ void __launch_bounds__(256) gemv_l1_kernel(
    const float* __restrict__ w10, const float* __restrict__ w00)
{
    __shared__ __align__(16) float sW[32 * 20];
    __shared__ float shm[32], shq[32];
    if (blockIdx.x < 256)
        gemv1_body<19, 20, 32>(blockIdx.x, d_g1, NT1, w10, d_xa1, OFF_S1L1,
                               sW, shm, shq);
    else
        gemv1_body<19, 20, 16>(blockIdx.x - 256, d_g0, NT0, w00, d_xa0,
                               OFF_S0L1, sW, shm, shq);
}

// ---------------- layer-2 body: BN/ReLU in + GEMV + stats + extremals ------
template<int CIN, int COUT, int NS, int COLOFF>
__device__ __forceinline__ void gemv2_body(
    int bid, const float* __restrict__ in, int ntot,
    const float* __restrict__ W,
    const float* __restrict__ gamma_, const float* __restrict__ beta_,
    float pN, int poff, int off,
    float* __restrict__ sW, float* __restrict__ sS, float* __restrict__ sB,
    float* __restrict__ shm, float* __restrict__ shq)
{
    for (int i = threadIdx.x; i < COUT * CIN; i += 256)
        sW[i] = W[i];
    for (int i = threadIdx.x; i < COUT; i += 256) { shm[i] = 0.f; shq[i] = 0.f; }
    for (int i = threadIdx.x; i < CIN; i += 256) {
        double inv  = 1.0 / (double)pN;
        double mean = d_sum[poff + i] * inv;
        double var  = d_sqs[poff + i] * inv - mean * mean;
        double sc   = (double)gamma_[i] * rsqrt(var + 1e-5);
        sS[i] = (float)sc;
        sB[i] = (float)((double)beta_[i] - mean * sc);
    }
    __syncthreads();

    int s    = (bid * 256 + threadIdx.x) * 2;
    int lane = threadIdx.x & 31;
    int q    = s / NS;

    float2 x[CIN];
    #pragma unroll
    for (int c = 0; c < CIN; c++) {
        float2 v = *(const float2*)&in[(size_t)c * ntot + s];
        v.x = fmaxf(fmaf(v.x, sS[c], sB[c]), 0.f);
        v.y = fmaxf(fmaf(v.y, sS[c], sB[c]), 0.f);
        x[c] = v;
    }

    const float4* sW4 = (const float4*)sW;
    #pragma unroll
    for (int o = 0; o < COUT; o++) {
        float ax = 0.f, ay = 0.f;
        #pragma unroll
        for (int c4 = 0; c4 < CIN / 4; c4++) {
            float4 wv = sW4[o * (CIN / 4) + c4];
            ax = fmaf(x[c4*4+0].x, wv.x, ax); ay = fmaf(x[c4*4+0].y, wv.x, ay);
            ax = fmaf(x[c4*4+1].x, wv.y, ax); ay = fmaf(x[c4*4+1].y, wv.y, ay);
            ax = fmaf(x[c4*4+2].x, wv.z, ax); ay = fmaf(x[c4*4+2].y, wv.z, ay);
            ax = fmaf(x[c4*4+3].x, wv.w, ax); ay = fmaf(x[c4*4+3].y, wv.w, ay);
        }
        float sm = ax + ay;
        float sq = fmaf(ax, ax, ay * ay);
        #pragma unroll
        for (int d = 16; d; d >>= 1) {
            sm += __shfl_down_sync(0xffffffffu, sm, d);
            sq += __shfl_down_sync(0xffffffffu, sq, d);
        }
        if (lane == 0) { atomicAdd(&shm[o], sm); atomicAdd(&shq[o], sq); }

        float mx = fmaxf(ax, ay), mn = fminf(ax, ay);
        #pragma unroll
        for (int d = 1; d < NS / 2; d <<= 1) {
            mx = fmaxf(mx, __shfl_xor_sync(0xffffffffu, mx, d));
            mn = fminf(mn, __shfl_xor_sync(0xffffffffu, mn, d));
        }
        if ((lane & (NS / 2 - 1)) == 0) {
            d_mx[q * 96 + COLOFF + o] = mx;
            d_mn[q * 96 + COLOFF + o] = mn;
        }
    }
    __syncthreads();
    if (threadIdx.x < COUT) {
        atomicAdd(&d_sum[off + threadIdx.x], (double)shm[threadIdx.x]);
        atomicAdd(&d_sqs[off + threadIdx.x], (double)shq[threadIdx.x]);
    }
}

// ---------------- kernel 3: fused layer-2 GEMVs + extremals ----------------
__global__ void __launch_bounds__(256) gemv_l2_kernel(
    const float* __restrict__ w11, const float* __restrict__ g10,
    const float* __restrict__ b10,
    const float* __restrict__ w01, const float* __restrict__ g00,
    const float* __restrict__ b00,
    const float* __restrict__ g11, const float* __restrict__ b11,
    const float* __restrict__ g01, const float* __restrict__ b01)
{
    __shared__ __align__(16) float sW[64 * 32];
    __shared__ float sS[32], sB[32], shm[64], shq[64];
    __shared__ int is_last;

    if (blockIdx.x < 256)
        gemv2_body<32, 64, NS1, 32>(blockIdx.x, d_xa1, NT1, w11, g10, b10,
                                    (float)NT1, OFF_S1L1, OFF_S1L2,
                                    sW, sS, sB, shm, shq);
    else
        gemv2_body<16, 32, NS0, 0>(blockIdx.x - 256, d_xa0, NT0, w01, g00, b00,
                                   (float)NT0, OFF_S0L1, OFF_S0L2,
                                   sW, sS, sB, shm, shq);

    if (threadIdx.x == 0) {
        __threadfence();
        is_last = (atomicAdd(&d_ctr2, 1u) == NB_L2 - 1);
    }
    __syncthreads();
    if (is_last && threadIdx.x < 96) {
        int t = threadIdx.x;
        int off; float pN, gam, bet;
        if (t < 32) { off = OFF_S0L2 + t; pN = (float)NT0; gam = g01[t]; bet = b01[t]; }
        else        { off = OFF_S1L2 + t - 32; pN = (float)NT1; gam = g11[t-32]; bet = b11[t-32]; }
        __threadfence();
        double inv  = 1.0 / (double)pN;
        double mean = d_sum[off] * inv;
        double var  = d_sqs[off] * inv - mean * mean;
        double sc   = (double)gam * rsqrt(var + 1e-5);
        d_p2s[t] = (float)sc;
        d_p2b[t] = (float)((double)bet - mean * sc);
    }
}

// ---------------- kernel 4: finalize (BN+ReLU, nxyz copy, zero-restore) ----
__global__ void __launch_bounds__(256) finalize_kernel(
    const float* __restrict__ nxyz, int out_off, float* __restrict__ out)
{
    int idx = blockIdx.x * 256 + threadIdx.x;

    // zero-restore sum/sqs/ctr2 for the next graph replay (they were last
    // read by gemv_l2, which completed before this kernel by stream order)
    if (idx < 144)      d_sum[idx] = 0.0;
    else if (idx < 288) d_sqs[idx - 144] = 0.0;
    else if (idx == 288) d_ctr2 = 0u;

    if (idx < out_off) {
        out[idx] = nxyz[idx];
        return;
    }
    int k = idx - out_off;
    if (k >= NQK * 96) return;
    int col = k % 96;
    float sc = d_p2s[col], bi = d_p2b[col];
    float v = (sc >= 0.f) ? d_mx[k] : d_mn[k];
    out[idx] = fmaxf(fmaf(v, sc, bi), 0.f);
}

// ---------------- launch ----------------------------------------------------
extern "C" void kernel_launch(void* const* d_in, const int* in_sizes, int n_in,
                              void* d_out, int out_size)
{
    const float* xyz  = (const float*)d_in[0];
    const float* nxyz = (const float*)d_in[2];
    const float* feat = (const float*)d_in[4];
    const float* w00 = (const float*)d_in[5];
    const float* g00 = (const float*)d_in[6];
    const float* b00 = (const float*)d_in[7];
    const float* w01 = (const float*)d_in[8];
    const float* g01 = (const float*)d_in[9];
    const float* b01 = (const float*)d_in[10];
    const float* w10 = (const float*)d_in[11];
    const float* g10 = (const float*)d_in[12];
    const float* b10 = (const float*)d_in[13];
    const float* w11 = (const float*)d_in[14];
    const float* g11 = (const float*)d_in[15];
    const float* b11 = (const float*)d_in[16];
    float* out = (float*)d_out;

    int out_off = out_size - NQK * 96;
    if (out_off < 0) out_off = 0;

    gridbuild_kernel<<<NBG, 256>>>(xyz);                              // 1
    bq_block_kernel<<<NQK, 128>>>(nxyz, feat);                        // 2
    gemv_l1_kernel<<<384, 256>>>(w10, w00);                           // 3
    gemv_l2_kernel<<<NB_L2, 256>>>(w11, g10, b10, w01, g00, b00,      // 4
                                   g11, b11, g01, b01);
    finalize_kernel<<<(out_off + NQK * 96 + 255) / 256, 256>>>(
        nxyz, out_off, out);                                          // 5
}